// round 2
// baseline (speedup 1.0000x reference)
#include <cuda_runtime.h>

// ---------------- problem constants ----------------
constexpr int NB   = 256;   // batch
constexpr int NT   = 576;   // history length
constexpr int NFT  = 24;    // future steps
constexpr int NM   = 32;    // m features
constexpr int NH   = 256;   // hidden
constexpr int NE   = 512;   // 2H
constexpr int KX1  = 544;   // 2H + M   (attn input)
constexpr int KX2  = 800;   // 512 ctx + 32 ff + 256 h  (gates input)
constexpr int G4   = 1024;  // 4H
constexpr float EPSC = 1e-6f;

// ---------------- scratch (device globals: no allocation allowed) ----------------
__device__ __align__(16) float g_X1[NB * KX1];        // [h0|h1|ff_t]
__device__ __align__(16) float g_tmp[NB * NT];
__device__ __align__(16) float g_logits[NB * NT];
__device__ __align__(16) float g_alpha[NB * NFT];
__device__ __align__(16) float g_X2[2 * NB * KX2];    // per dir: [ctx|ff_t|h_d]
__device__ __align__(16) float g_gates[2 * NB * G4];
__device__ __align__(16) float g_c[2 * NB * NH];
__device__ __align__(16) float g_hh[NB * NE];
__device__ __align__(16) float g_Wcat[2 * G4 * KX2];  // [W_ih | W_hh] per dir
__device__ __align__(16) float g_bias2[2 * G4];

__device__ __forceinline__ float sigm(float x) { return 1.0f / (1.0f + expf(-x)); }

// ---------------- one-time setup: out init, c copy, X1/X2 initial fill ----------------
__global__ void setup_kernel(const float* __restrict__ hidden, const float* __restrict__ cell,
                             const float* __restrict__ ff, const float* __restrict__ fb2,
                             float* __restrict__ out, float* __restrict__ c,
                             float* __restrict__ X1, float* __restrict__ X2)
{
    const int N0 = NB * NFT;       // out init
    const int N1 = 2 * NB * NH;    // c copy
    const int N2 = NB * KX1;       // X1 fill
    const int N3 = 2 * NB * 288;   // X2 [ff|h] fill
    const int total = N0 + N1 + N2 + N3;
    for (int i = blockIdx.x * blockDim.x + threadIdx.x; i < total; i += gridDim.x * blockDim.x) {
        int r = i;
        if (r < N0) { out[r] = fb2[0]; continue; }
        r -= N0;
        if (r < N1) { c[r] = cell[r]; continue; }
        r -= N1;
        if (r < N2) {
            int b = r / KX1, k = r % KX1;
            float v;
            if (k < 512) v = hidden[(k < 256 ? 0 : 1) * NB * NH + b * NH + (k & 255)];
            else         v = ff[b * NFT * NM + (k - 512)];
            X1[r] = v; continue;
        }
        r -= N2;
        int d = r / (NB * 288); int r2 = r % (NB * 288);
        int b = r2 / 288, k = r2 % 288;
        float v = (k < NM) ? ff[b * NFT * NM + k]
                           : hidden[d * NB * NH + b * NH + (k - NM)];
        X2[(long)(d * NB + b) * KX2 + 512 + k] = v;
    }
}

// ---------------- alpha: period-similarity softmax (once) ----------------
__global__ void alpha_kernel(const float* __restrict__ ff, const float* __restrict__ fh,
                             float* __restrict__ alpha)
{
    int b = blockIdx.x, tid = threadIdx.x;  // 576 threads
    int f = tid / 24, p = tid % 24;
    __shared__ float dist[24][24];
    __shared__ float dp[24];
    const float* x = ff + (b * NFT + f) * NM;
    const float* y = fh + ((long)b * NT + p * 24 + f) * NM;
    float s = 0.0f;
#pragma unroll
    for (int m = 0; m < NM; m++) { float d = x[m] - y[m] + EPSC; s += d * d; }
    dist[f][p] = sqrtf(s);
    __syncthreads();
    if (p == 0) { float t = 0.0f; for (int q = 0; q < 24; q++) t += dist[f][q]; dp[f] = 1.0f / t; }
    __syncthreads();
    if (tid == 0) {
        float mx = -1e30f;
        for (int q = 0; q < 24; q++) mx = fmaxf(mx, dp[q]);
        float e[24]; float ss = 0.0f;
        for (int q = 0; q < 24; q++) { e[q] = expf(dp[q] - mx); ss += e[q]; }
        float inv = 1.0f / ss;
        for (int q = 0; q < 24; q++) alpha[b * 24 + q] = e[q] * inv;
    }
}

// ---------------- pack [W_ih | W_hh] and combined bias (once) ----------------
__global__ void wcat_kernel(const float* __restrict__ Wih, const float* __restrict__ Whh,
                            const float* __restrict__ bih, const float* __restrict__ bhh,
                            float* __restrict__ Wcat, float* __restrict__ bias2)
{
    const int total = 2 * G4 * KX2;
    for (int i = blockIdx.x * blockDim.x + threadIdx.x; i < total; i += gridDim.x * blockDim.x) {
        int d = i / (G4 * KX2); int r = i % (G4 * KX2);
        int n = r / KX2, k = r % KX2;
        Wcat[i] = (k < KX1) ? Wih[(long)(d * G4 + n) * KX1 + k]
                            : Whh[(long)(d * G4 + n) * NH + (k - KX1)];
    }
    int tid = blockIdx.x * blockDim.x + threadIdx.x;
    if (tid < 2 * G4) bias2[tid] = bih[tid] + bhh[tid];
}

// ---------------- generic tiled GEMM: C = act(A @ W^T + bias) ----------------
// A[M,K] rowmajor, W[N,K] rowmajor, C[M,N]. 64x64x16 tiles, 256 threads, 4x4/thread.
// Batched via blockIdx.z with element strides. ACT: 0 none, 1 tanh, 2 relu.
template<int ACT>
__global__ __launch_bounds__(256) void gemm_kernel(
    const float* __restrict__ A, const float* __restrict__ W,
    const float* __restrict__ bias, float* __restrict__ C,
    int K, int N, long sA, long sW, long sB, long sC)
{
    A += blockIdx.z * sA; W += blockIdx.z * sW; bias += blockIdx.z * sB; C += blockIdx.z * sC;
    __shared__ float As[16][68];
    __shared__ float Ws[16][68];
    const int tid = threadIdx.x;
    const int m0 = blockIdx.x * 64, n0 = blockIdx.y * 64;
    const int ty = tid >> 4, tx = tid & 15;
    const int lr = tid >> 2, lc = (tid & 3) << 2;
    float acc[4][4] = {};
    const float* Ap = A + (long)(m0 + lr) * K + lc;
    const float* Wp = W + (long)(n0 + lr) * K + lc;
    for (int k0 = 0; k0 < K; k0 += 16) {
        float4 av = *(const float4*)(Ap + k0);
        float4 wv = *(const float4*)(Wp + k0);
        As[lc + 0][lr] = av.x; As[lc + 1][lr] = av.y; As[lc + 2][lr] = av.z; As[lc + 3][lr] = av.w;
        Ws[lc + 0][lr] = wv.x; Ws[lc + 1][lr] = wv.y; Ws[lc + 2][lr] = wv.z; Ws[lc + 3][lr] = wv.w;
        __syncthreads();
#pragma unroll
        for (int kk = 0; kk < 16; kk++) {
            float a[4], w[4];
#pragma unroll
            for (int i = 0; i < 4; i++) a[i] = As[kk][ty * 4 + i];
#pragma unroll
            for (int j = 0; j < 4; j++) w[j] = Ws[kk][tx * 4 + j];
#pragma unroll
            for (int i = 0; i < 4; i++)
#pragma unroll
                for (int j = 0; j < 4; j++)
                    acc[i][j] += a[i] * w[j];
        }
        __syncthreads();
    }
#pragma unroll
    for (int i = 0; i < 4; i++) {
        int m = m0 + ty * 4 + i;
#pragma unroll
        for (int j = 0; j < 4; j++) {
            int n = n0 + tx * 4 + j;
            float v = acc[i][j] + bias[n];
            if (ACT == 1) v = tanhf(v);
            if (ACT == 2) v = fmaxf(v, 0.0f);
            C[(long)m * N + n] = v;
        }
    }
}

// ---------------- fc_final fused: relu(A@W1^T+b1) dot W2, atomicAdd into out[b,t] ----------------
__global__ __launch_bounds__(256) void gemm_fc_kernel(
    const float* __restrict__ A, const float* __restrict__ W,
    const float* __restrict__ bias, const float* __restrict__ w2,
    float* __restrict__ out, int K, int N, int tstep)
{
    __shared__ float As[16][68];
    __shared__ float Ws[16][68];
    const int tid = threadIdx.x;
    const int m0 = blockIdx.x * 64, n0 = blockIdx.y * 64;
    const int ty = tid >> 4, tx = tid & 15;
    const int lr = tid >> 2, lc = (tid & 3) << 2;
    float acc[4][4] = {};
    const float* Ap = A + (long)(m0 + lr) * K + lc;
    const float* Wp = W + (long)(n0 + lr) * K + lc;
    for (int k0 = 0; k0 < K; k0 += 16) {
        float4 av = *(const float4*)(Ap + k0);
        float4 wv = *(const float4*)(Wp + k0);
        As[lc + 0][lr] = av.x; As[lc + 1][lr] = av.y; As[lc + 2][lr] = av.z; As[lc + 3][lr] = av.w;
        Ws[lc + 0][lr] = wv.x; Ws[lc + 1][lr] = wv.y; Ws[lc + 2][lr] = wv.z; Ws[lc + 3][lr] = wv.w;
        __syncthreads();
#pragma unroll
        for (int kk = 0; kk < 16; kk++) {
            float a[4], w[4];
#pragma unroll
            for (int i = 0; i < 4; i++) a[i] = As[kk][ty * 4 + i];
#pragma unroll
            for (int j = 0; j < 4; j++) w[j] = Ws[kk][tx * 4 + j];
#pragma unroll
            for (int i = 0; i < 4; i++)
#pragma unroll
                for (int j = 0; j < 4; j++)
                    acc[i][j] += a[i] * w[j];
        }
        __syncthreads();
    }
    float part[4];
#pragma unroll
    for (int i = 0; i < 4; i++) {
        float s = 0.0f;
#pragma unroll
        for (int j = 0; j < 4; j++) {
            int n = n0 + tx * 4 + j;
            float v = fmaxf(acc[i][j] + bias[n], 0.0f);
            s += v * w2[n];
        }
        part[i] = s;
    }
    __syncthreads();
    float* red = &As[0][0];  // 1088 floats >= 64*16
#pragma unroll
    for (int i = 0; i < 4; i++) red[(ty * 4 + i) * 16 + tx] = part[i];
    __syncthreads();
    if (tid < 64) {
        float s = 0.0f;
#pragma unroll
        for (int x = 0; x < 16; x++) s += red[tid * 16 + x];
        atomicAdd(&out[(m0 + tid) * NFT + tstep], s);
    }
}

// ---------------- ctx: row softmax (*alpha) folded + stream enc; write ctx into both X2 slices ----------------
__global__ __launch_bounds__(128) void ctx_kernel(
    const float* __restrict__ logits, const float* __restrict__ alpha,
    const float* __restrict__ enc, float* __restrict__ X2)
{
    const int b = blockIdx.y;
    const int e0 = blockIdx.x * 128;
    const int tid = threadIdx.x;
    __shared__ float wt[NT];
    __shared__ float sred[4];
    const float* lrow = logits + b * NT;

    float mx = -1e30f;
    for (int t = tid; t < NT; t += 128) mx = fmaxf(mx, lrow[t]);
#pragma unroll
    for (int o = 16; o > 0; o >>= 1) mx = fmaxf(mx, __shfl_xor_sync(0xffffffffu, mx, o));
    if ((tid & 31) == 0) sred[tid >> 5] = mx;
    __syncthreads();
    mx = fmaxf(fmaxf(sred[0], sred[1]), fmaxf(sred[2], sred[3]));
    __syncthreads();  // protect sred reuse

    float s = 0.0f;
    for (int t = tid; t < NT; t += 128) { float e = expf(lrow[t] - mx); wt[t] = e; s += e; }
#pragma unroll
    for (int o = 16; o > 0; o >>= 1) s += __shfl_xor_sync(0xffffffffu, s, o);
    if ((tid & 31) == 0) sred[tid >> 5] = s;
    __syncthreads();
    s = sred[0] + sred[1] + sred[2] + sred[3];
    float inv = 1.0f / s;
    for (int t = tid; t < NT; t += 128) wt[t] *= inv * alpha[b * 24 + t / 24];
    __syncthreads();

    const float* ebase = enc + ((long)b * NT) * NE + e0 + tid;
    float a0 = 0, a1 = 0, a2 = 0, a3 = 0;
#pragma unroll 2
    for (int t = 0; t < NT; t += 4) {
        a0 += wt[t + 0] * ebase[(long)(t + 0) * NE];
        a1 += wt[t + 1] * ebase[(long)(t + 1) * NE];
        a2 += wt[t + 2] * ebase[(long)(t + 2) * NE];
        a3 += wt[t + 3] * ebase[(long)(t + 3) * NE];
    }
    float acc = (a0 + a1) + (a2 + a3);
    X2[(long)b * KX2 + e0 + tid] = acc;               // dir 0
    X2[(long)(NB + b) * KX2 + e0 + tid] = acc;        // dir 1
}

// ---------------- LSTM cell + write-forward of h (and ff[t+1]) into X1/X2/hh ----------------
__global__ __launch_bounds__(256) void lstm_kernel(
    const float* __restrict__ gates, float* __restrict__ c,
    float* __restrict__ X1, float* __restrict__ X2,
    float* __restrict__ hh, const float* __restrict__ ffn)
{
    int idx = blockIdx.x * 256 + threadIdx.x;   // 2*256*256
    int j = idx & 255, b = (idx >> 8) & 255, d = idx >> 16;
    const float* g = gates + (long)(d * NB + b) * G4;
    float ig = sigm(g[j]);
    float fg = sigm(g[j + 256]);
    float gg = tanhf(g[j + 512]);
    float og = sigm(g[j + 768]);
    float cn = fg * c[idx] + ig * gg;
    float hn = og * tanhf(cn);
    c[idx] = cn;
    X2[(long)(d * NB + b) * KX2 + 544 + j] = hn;
    hh[b * NE + d * NH + j] = hn;
    X1[b * KX1 + d * NH + j] = hn;
    if (ffn != nullptr && j < NM) {
        float v = ffn[b * NFT * NM + j];
        X2[(long)(d * NB + b) * KX2 + 512 + j] = v;
        if (d == 0) X1[b * KX1 + 512 + j] = v;
    }
}

// ---------------- launch ----------------
extern "C" void kernel_launch(void* const* d_in, const int* in_sizes, int n_in,
                              void* d_out, int out_size)
{
    const float* enc    = (const float*)d_in[0];
    const float* fhist  = (const float*)d_in[1];
    /* d_in[2] = y_history, unused */
    const float* ffut   = (const float*)d_in[3];
    const float* hidden = (const float*)d_in[4];
    const float* cell   = (const float*)d_in[5];
    const float* aW1    = (const float*)d_in[6];
    const float* ab1    = (const float*)d_in[7];
    const float* aW2    = (const float*)d_in[8];
    const float* ab2    = (const float*)d_in[9];
    const float* Wih    = (const float*)d_in[10];
    const float* Whh    = (const float*)d_in[11];
    const float* bih    = (const float*)d_in[12];
    const float* bhh    = (const float*)d_in[13];
    const float* fW1    = (const float*)d_in[14];
    const float* fb1    = (const float*)d_in[15];
    const float* fW2    = (const float*)d_in[16];
    const float* fb2    = (const float*)d_in[17];
    float* out = (float*)d_out;

    float *pX1, *pTmp, *pLog, *pAlpha, *pX2, *pGates, *pC, *pHH, *pWcat, *pBias2;
    cudaGetSymbolAddress((void**)&pX1, g_X1);
    cudaGetSymbolAddress((void**)&pTmp, g_tmp);
    cudaGetSymbolAddress((void**)&pLog, g_logits);
    cudaGetSymbolAddress((void**)&pAlpha, g_alpha);
    cudaGetSymbolAddress((void**)&pX2, g_X2);
    cudaGetSymbolAddress((void**)&pGates, g_gates);
    cudaGetSymbolAddress((void**)&pC, g_c);
    cudaGetSymbolAddress((void**)&pHH, g_hh);
    cudaGetSymbolAddress((void**)&pWcat, g_Wcat);
    cudaGetSymbolAddress((void**)&pBias2, g_bias2);

    setup_kernel<<<512, 256>>>(hidden, cell, ffut, fb2, out, pC, pX1, pX2);
    alpha_kernel<<<NB, 576>>>(ffut, fhist, pAlpha);
    wcat_kernel<<<1024, 256>>>(Wih, Whh, bih, bhh, pWcat, pBias2);

    for (int t = 0; t < NFT; t++) {
        // attn: tmp = tanh(X1 @ W1^T + b1)
        gemm_kernel<1><<<dim3(NB / 64, NT / 64, 1), 256>>>(pX1, aW1, ab1, pTmp, KX1, NT, 0, 0, 0, 0);
        // logits = tmp @ W2^T + b2
        gemm_kernel<0><<<dim3(NB / 64, NT / 64, 1), 256>>>(pTmp, aW2, ab2, pLog, NT, NT, 0, 0, 0, 0);
        // ctx (softmax * alpha folded) -> X2[:, 0:512] for both dirs
        ctx_kernel<<<dim3(NE / 128, NB, 1), 128>>>(pLog, pAlpha, enc, pX2);
        // gates = X2 @ Wcat^T + bias2, both directions via z
        gemm_kernel<0><<<dim3(NB / 64, G4 / 64, 2), 256>>>(
            pX2, pWcat, pBias2, pGates, KX2, G4,
            (long)NB * KX2, (long)G4 * KX2, (long)G4, (long)NB * G4);
        // LSTM update; also forwards h / ff[t+1] into X1, X2, hh
        const float* ffn = (t + 1 < NFT) ? (ffut + (t + 1) * NM) : nullptr;
        lstm_kernel<<<2 * NB * NH / 256, 256>>>(pGates, pC, pX1, pX2, pHH, ffn);
        // y[:, t] = relu(hh @ fW1^T + fb1) @ fW2^T (+fb2 pre-initialized)
        gemm_fc_kernel<<<dim3(NB / 64, NH / 64, 1), 256>>>(pHH, fW1, fb1, fW2, out, NE, NH, t);
    }
    (void)in_sizes; (void)n_in; (void)out_size;
}

// round 4
// speedup vs baseline: 1.3292x; 1.3292x over previous
#include <cuda_runtime.h>
#include <cuda_fp16.h>
#include <mma.h>
using namespace nvcuda;

// ---------------- problem constants ----------------
constexpr int NB   = 256;
constexpr int NT   = 576;
constexpr int NFT  = 24;
constexpr int NM   = 32;
constexpr int NH   = 256;
constexpr int NE   = 512;
constexpr int KX1  = 544;
constexpr int KX2  = 800;
constexpr int G4   = 1024;
constexpr float EPSC = 1e-6f;

constexpr int BM = 32, BN = 64;
constexpr int SKA = 24;   // smem half row stride (48B: 16B-aligned rows, spread banks)

// ---------------- scratch (device globals) ----------------
// activation buffers: [hi | lo] halves, lo at +size
__device__ __align__(16) __half g_X1h[2 * NB * KX1];
__device__ __align__(16) __half g_tmph[2 * NB * NT];
__device__ __align__(16) __half g_X2h[2 * 2 * NB * KX2];
__device__ __align__(16) __half g_hhh[2 * NB * NE];
// weights split
__device__ __align__(16) __half g_aW1h[2 * NT * KX1];
__device__ __align__(16) __half g_aW2h[2 * NT * NT];
__device__ __align__(16) __half g_Wcath[2 * 2 * G4 * KX2];
__device__ __align__(16) __half g_fW1h[2 * NH * NE];
// encoder in fp16 (hi only)
__device__ __align__(16) __half g_ench[(long)NB * NT * NE];
// fp32 state
__device__ __align__(16) float g_logits[NB * NT];
__device__ __align__(16) float g_alpha[NB * NFT];
__device__ __align__(16) float g_gates[2 * NB * G4];
__device__ __align__(16) float g_c[2 * NB * NH];
__device__ __align__(16) float g_bias2[2 * G4];

__device__ __forceinline__ float sigm(float x) { return 1.0f / (1.0f + expf(-x)); }
__device__ __forceinline__ void fsplit(float v, __half& hi, __half& lo) {
    hi = __float2half(v);
    lo = __float2half(v - __half2float(hi));
}

// ---------------- one-time setup ----------------
__global__ void setup_kernel(const float* __restrict__ hidden, const float* __restrict__ cell,
                             const float* __restrict__ ff, const float* __restrict__ fb2,
                             float* __restrict__ out, float* __restrict__ c,
                             __half* __restrict__ X1, __half* __restrict__ X2)
{
    const int N0 = NB * NFT;
    const int N1 = 2 * NB * NH;
    const int N2 = NB * KX1;
    const int N3 = 2 * NB * 288;
    const int total = N0 + N1 + N2 + N3;
    const int OX1 = NB * KX1;           // lo offset in X1
    const int OX2 = 2 * NB * KX2;       // lo offset in X2
    for (int i = blockIdx.x * blockDim.x + threadIdx.x; i < total; i += gridDim.x * blockDim.x) {
        int r = i;
        if (r < N0) { out[r] = fb2[0]; continue; }
        r -= N0;
        if (r < N1) { c[r] = cell[r]; continue; }
        r -= N1;
        if (r < N2) {
            int b = r / KX1, k = r % KX1;
            float v;
            if (k < 512) v = hidden[(k < 256 ? 0 : 1) * NB * NH + b * NH + (k & 255)];
            else         v = ff[b * NFT * NM + (k - 512)];
            __half h, l; fsplit(v, h, l);
            X1[r] = h; X1[OX1 + r] = l; continue;
        }
        r -= N2;
        int d = r / (NB * 288); int r2 = r % (NB * 288);
        int b = r2 / 288, k = r2 % 288;
        float v = (k < NM) ? ff[b * NFT * NM + k]
                           : hidden[d * NB * NH + b * NH + (k - NM)];
        int o = (d * NB + b) * KX2 + 512 + k;
        __half h, l; fsplit(v, h, l);
        X2[o] = h; X2[OX2 + o] = l;
    }
}

// ---------------- alpha (once) ----------------
__global__ void alpha_kernel(const float* __restrict__ ff, const float* __restrict__ fh,
                             float* __restrict__ alpha)
{
    int b = blockIdx.x, tid = threadIdx.x;
    int f = tid / 24, p = tid % 24;
    __shared__ float dist[24][24];
    __shared__ float dp[24];
    const float* x = ff + (b * NFT + f) * NM;
    const float* y = fh + ((long)b * NT + p * 24 + f) * NM;
    float s = 0.0f;
#pragma unroll
    for (int m = 0; m < NM; m++) { float d = x[m] - y[m] + EPSC; s += d * d; }
    dist[f][p] = sqrtf(s);
    __syncthreads();
    if (p == 0) { float t = 0.0f; for (int q = 0; q < 24; q++) t += dist[f][q]; dp[f] = 1.0f / t; }
    __syncthreads();
    if (tid == 0) {
        float mx = -1e30f;
        for (int q = 0; q < 24; q++) mx = fmaxf(mx, dp[q]);
        float e[24]; float ss = 0.0f;
        for (int q = 0; q < 24; q++) { e[q] = expf(dp[q] - mx); ss += e[q]; }
        float inv = 1.0f / ss;
        for (int q = 0; q < 24; q++) alpha[b * 24 + q] = e[q] * inv;
    }
}

// ---------------- pack [W_ih | W_hh] split + combined bias (once) ----------------
__global__ void wcat_kernel(const float* __restrict__ Wih, const float* __restrict__ Whh,
                            const float* __restrict__ bih, const float* __restrict__ bhh,
                            __half* __restrict__ Wcat, float* __restrict__ bias2)
{
    const int total = 2 * G4 * KX2;
    for (int i = blockIdx.x * blockDim.x + threadIdx.x; i < total; i += gridDim.x * blockDim.x) {
        int d = i / (G4 * KX2); int r = i % (G4 * KX2);
        int n = r / KX2, k = r % KX2;
        float v = (k < KX1) ? Wih[(long)(d * G4 + n) * KX1 + k]
                            : Whh[(long)(d * G4 + n) * NH + (k - KX1)];
        __half h, l; fsplit(v, h, l);
        Wcat[i] = h; Wcat[total + i] = l;
    }
    int tid = blockIdx.x * blockDim.x + threadIdx.x;
    if (tid < 2 * G4) bias2[tid] = bih[tid] + bhh[tid];
}

// ---------------- generic converters ----------------
__global__ void conv_split(const float* __restrict__ src, __half* __restrict__ dst, int n)
{
    for (int i = blockIdx.x * blockDim.x + threadIdx.x; i < n; i += gridDim.x * blockDim.x) {
        __half h, l; fsplit(src[i], h, l);
        dst[i] = h; dst[n + i] = l;
    }
}

__global__ void conv_half4(const float4* __restrict__ src, uint2* __restrict__ dst, int n4)
{
    for (int i = blockIdx.x * blockDim.x + threadIdx.x; i < n4; i += gridDim.x * blockDim.x) {
        float4 v = src[i];
        __half2 a = __floats2half2_rn(v.x, v.y);
        __half2 b = __floats2half2_rn(v.z, v.w);
        uint2 u;
        u.x = *reinterpret_cast<unsigned*>(&a);
        u.y = *reinterpret_cast<unsigned*>(&b);
        dst[i] = u;
    }
}

// ---------------- split-fp16 tensor-core GEMM: C = act(A @ W^T + bias) ----------------
// A[M,K] split halves rowmajor, W[N,K] split halves rowmajor. Block tile 32x64, 4 warps.
// 3-term mma: AhWh + AhWl + AlWh (fp32 accumulate) -> ~fp32 accuracy.
template<int ACT, int OUTH>
__global__ __launch_bounds__(128) void hgemm(
    const __half* __restrict__ Ahi, const __half* __restrict__ Alo,
    const __half* __restrict__ Whi, const __half* __restrict__ Wlo,
    const float* __restrict__ bias, float* __restrict__ Cf,
    __half* __restrict__ Chi, __half* __restrict__ Clo,
    int K, int N, long sA, long sW, long sB, long sC)
{
    long z = blockIdx.z;
    Ahi += z * sA; Alo += z * sA; Whi += z * sW; Wlo += z * sW; bias += z * sB;
    __shared__ __half As[2][BM][SKA];
    __shared__ __half Ws[2][BN][SKA];
    __shared__ float Cs[BM][BN + 4];
    const int tid = threadIdx.x;
    const int m0 = blockIdx.x * BM, n0 = blockIdx.y * BN;
    const int warp = tid >> 5, wm = warp >> 1, wn = warp & 1;
    wmma::fragment<wmma::accumulator, 16, 16, 16, float> c0, c1;
    wmma::fill_fragment(c0, 0.0f); wmma::fill_fragment(c1, 0.0f);
    const int lr = tid >> 2, lc = (tid & 3) * 4;
    const __half* Ah  = Ahi + (long)(m0 + lr) * K + lc;
    const __half* Al  = Alo + (long)(m0 + lr) * K + lc;
    const __half* Wh0 = Whi + (long)(n0 + lr) * K + lc;
    const __half* Wl0 = Wlo + (long)(n0 + lr) * K + lc;
    const __half* Wh1 = Whi + (long)(n0 + lr + 32) * K + lc;
    const __half* Wl1 = Wlo + (long)(n0 + lr + 32) * K + lc;
    for (int k0 = 0; k0 < K; k0 += 16) {
        *(uint2*)&As[0][lr][lc]      = *(const uint2*)(Ah + k0);
        *(uint2*)&As[1][lr][lc]      = *(const uint2*)(Al + k0);
        *(uint2*)&Ws[0][lr][lc]      = *(const uint2*)(Wh0 + k0);
        *(uint2*)&Ws[1][lr][lc]      = *(const uint2*)(Wl0 + k0);
        *(uint2*)&Ws[0][lr + 32][lc] = *(const uint2*)(Wh1 + k0);
        *(uint2*)&Ws[1][lr + 32][lc] = *(const uint2*)(Wl1 + k0);
        __syncthreads();
        wmma::fragment<wmma::matrix_a, 16, 16, 16, __half, wmma::row_major> ah, al;
        wmma::load_matrix_sync(ah, &As[0][wm * 16][0], SKA);
        wmma::load_matrix_sync(al, &As[1][wm * 16][0], SKA);
        wmma::fragment<wmma::matrix_b, 16, 16, 16, __half, wmma::col_major> bh, bl;
        wmma::load_matrix_sync(bh, &Ws[0][wn * 32][0], SKA);
        wmma::load_matrix_sync(bl, &Ws[1][wn * 32][0], SKA);
        wmma::mma_sync(c0, ah, bh, c0);
        wmma::mma_sync(c0, ah, bl, c0);
        wmma::mma_sync(c0, al, bh, c0);
        wmma::load_matrix_sync(bh, &Ws[0][wn * 32 + 16][0], SKA);
        wmma::load_matrix_sync(bl, &Ws[1][wn * 32 + 16][0], SKA);
        wmma::mma_sync(c1, ah, bh, c1);
        wmma::mma_sync(c1, ah, bl, c1);
        wmma::mma_sync(c1, al, bh, c1);
        __syncthreads();
    }
    wmma::store_matrix_sync(&Cs[wm * 16][wn * 32], c0, BN + 4, wmma::mem_row_major);
    wmma::store_matrix_sync(&Cs[wm * 16][wn * 32 + 16], c1, BN + 4, wmma::mem_row_major);
    __syncthreads();
    for (int idx = tid; idx < BM * BN; idx += 128) {
        int m = idx >> 6, n = idx & 63;
        float v = Cs[m][n] + bias[n0 + n];
        if (ACT == 1) v = tanhf(v);
        long o = (long)(m0 + m) * N + n0 + n + z * sC;
        if (OUTH) {
            __half h = __float2half(v);
            Chi[o] = h;
            Clo[o] = __float2half(v - __half2float(h));
        } else {
            Cf[o] = v;
        }
    }
}

// ---------------- fc_final fused: relu(A@W1^T+b1) dot w2 -> atomicAdd out[b,t] ----------------
__global__ __launch_bounds__(128) void hgemm_fc(
    const __half* __restrict__ Ahi, const __half* __restrict__ Alo,
    const __half* __restrict__ Whi, const __half* __restrict__ Wlo,
    const float* __restrict__ bias, const float* __restrict__ w2,
    float* __restrict__ out, int K, int tstep)
{
    __shared__ __half As[2][BM][SKA];
    __shared__ __half Ws[2][BN][SKA];
    __shared__ float Cs[BM][BN + 4];
    __shared__ float red[128];
    const int tid = threadIdx.x;
    const int m0 = blockIdx.x * BM, n0 = blockIdx.y * BN;
    const int warp = tid >> 5, wm = warp >> 1, wn = warp & 1;
    wmma::fragment<wmma::accumulator, 16, 16, 16, float> c0, c1;
    wmma::fill_fragment(c0, 0.0f); wmma::fill_fragment(c1, 0.0f);
    const int lr = tid >> 2, lc = (tid & 3) * 4;
    const __half* Ah  = Ahi + (long)(m0 + lr) * K + lc;
    const __half* Al  = Alo + (long)(m0 + lr) * K + lc;
    const __half* Wh0 = Whi + (long)(n0 + lr) * K + lc;
    const __half* Wl0 = Wlo + (long)(n0 + lr) * K + lc;
    const __half* Wh1 = Whi + (long)(n0 + lr + 32) * K + lc;
    const __half* Wl1 = Wlo + (long)(n0 + lr + 32) * K + lc;
    for (int k0 = 0; k0 < K; k0 += 16) {
        *(uint2*)&As[0][lr][lc]      = *(const uint2*)(Ah + k0);
        *(uint2*)&As[1][lr][lc]      = *(const uint2*)(Al + k0);
        *(uint2*)&Ws[0][lr][lc]      = *(const uint2*)(Wh0 + k0);
        *(uint2*)&Ws[1][lr][lc]      = *(const uint2*)(Wl0 + k0);
        *(uint2*)&Ws[0][lr + 32][lc] = *(const uint2*)(Wh1 + k0);
        *(uint2*)&Ws[1][lr + 32][lc] = *(const uint2*)(Wl1 + k0);
        __syncthreads();
        wmma::fragment<wmma::matrix_a, 16, 16, 16, __half, wmma::row_major> ah, al;
        wmma::load_matrix_sync(ah, &As[0][wm * 16][0], SKA);
        wmma::load_matrix_sync(al, &As[1][wm * 16][0], SKA);
        wmma::fragment<wmma::matrix_b, 16, 16, 16, __half, wmma::col_major> bh, bl;
        wmma::load_matrix_sync(bh, &Ws[0][wn * 32][0], SKA);
        wmma::load_matrix_sync(bl, &Ws[1][wn * 32][0], SKA);
        wmma::mma_sync(c0, ah, bh, c0);
        wmma::mma_sync(c0, ah, bl, c0);
        wmma::mma_sync(c0, al, bh, c0);
        wmma::load_matrix_sync(bh, &Ws[0][wn * 32 + 16][0], SKA);
        wmma::load_matrix_sync(bl, &Ws[1][wn * 32 + 16][0], SKA);
        wmma::mma_sync(c1, ah, bh, c1);
        wmma::mma_sync(c1, ah, bl, c1);
        wmma::mma_sync(c1, al, bh, c1);
        __syncthreads();
    }
    wmma::store_matrix_sync(&Cs[wm * 16][wn * 32], c0, BN + 4, wmma::mem_row_major);
    wmma::store_matrix_sync(&Cs[wm * 16][wn * 32 + 16], c1, BN + 4, wmma::mem_row_major);
    __syncthreads();
    const int r = tid >> 2, g = tid & 3;
    float s = 0.0f;
#pragma unroll
    for (int j = 0; j < 16; j++) {
        int n = g * 16 + j;
        float v = fmaxf(Cs[r][n] + bias[n0 + n], 0.0f);
        s += v * w2[n0 + n];
    }
    red[tid] = s;
    __syncthreads();
    if (tid < 32) {
        float t = red[tid * 4] + red[tid * 4 + 1] + red[tid * 4 + 2] + red[tid * 4 + 3];
        atomicAdd(&out[(m0 + tid) * NFT + tstep], t);
    }
}

// ---------------- ctx: softmax(*alpha) + stream fp16 enc; writes split ctx both dirs ----------------
__global__ __launch_bounds__(128) void ctx_kernel(
    const float* __restrict__ logits, const float* __restrict__ alpha,
    const __half* __restrict__ ench, __half* __restrict__ X2hi, __half* __restrict__ X2lo)
{
    const int b = blockIdx.y;
    const int e0 = blockIdx.x * 256;   // 256 elems per block, 2 per thread
    const int tid = threadIdx.x;
    __shared__ float wt[NT];
    __shared__ float sred[4];
    const float* lrow = logits + b * NT;

    float mx = -1e30f;
    for (int t = tid; t < NT; t += 128) mx = fmaxf(mx, lrow[t]);
#pragma unroll
    for (int o = 16; o > 0; o >>= 1) mx = fmaxf(mx, __shfl_xor_sync(0xffffffffu, mx, o));
    if ((tid & 31) == 0) sred[tid >> 5] = mx;
    __syncthreads();
    mx = fmaxf(fmaxf(sred[0], sred[1]), fmaxf(sred[2], sred[3]));
    __syncthreads();

    float s = 0.0f;
    for (int t = tid; t < NT; t += 128) { float e = expf(lrow[t] - mx); wt[t] = e; s += e; }
#pragma unroll
    for (int o = 16; o > 0; o >>= 1) s += __shfl_xor_sync(0xffffffffu, s, o);
    if ((tid & 31) == 0) sred[tid >> 5] = s;
    __syncthreads();
    s = sred[0] + sred[1] + sred[2] + sred[3];
    float inv = 1.0f / s;
    for (int t = tid; t < NT; t += 128) wt[t] *= inv * alpha[b * 24 + t / 24];
    __syncthreads();

    const __half2* eb = (const __half2*)(ench + ((long)b * NT) * NE + e0) + tid;
    float ax0 = 0, ay0 = 0, ax1 = 0, ay1 = 0;
#pragma unroll 2
    for (int t = 0; t < NT; t += 2) {
        float2 v0 = __half22float2(eb[(t + 0) * (NE / 2)]);
        float2 v1 = __half22float2(eb[(t + 1) * (NE / 2)]);
        ax0 += wt[t + 0] * v0.x; ay0 += wt[t + 0] * v0.y;
        ax1 += wt[t + 1] * v1.x; ay1 += wt[t + 1] * v1.y;
    }
    float vx = ax0 + ax1, vy = ay0 + ay1;
    __half hx, lx, hy, ly;
    fsplit(vx, hx, lx); fsplit(vy, hy, ly);
    long o0 = (long)b * KX2 + e0 + 2 * tid;
    long o1 = (long)(NB + b) * KX2 + e0 + 2 * tid;
    X2hi[o0] = hx; X2hi[o0 + 1] = hy; X2lo[o0] = lx; X2lo[o0 + 1] = ly;
    X2hi[o1] = hx; X2hi[o1 + 1] = hy; X2lo[o1] = lx; X2lo[o1 + 1] = ly;
}

// ---------------- LSTM cell + forward h (and ff[t+1]) as split halves ----------------
__global__ __launch_bounds__(256) void lstm_kernel(
    const float* __restrict__ gates, float* __restrict__ c,
    __half* __restrict__ X1hi, __half* __restrict__ X1lo,
    __half* __restrict__ X2hi, __half* __restrict__ X2lo,
    __half* __restrict__ hhhi, __half* __restrict__ hhlo,
    const float* __restrict__ ffn)
{
    int idx = blockIdx.x * 256 + threadIdx.x;   // 2*256*256
    int j = idx & 255, b = (idx >> 8) & 255, d = idx >> 16;
    const float* g = gates + (long)(d * NB + b) * G4;
    float ig = sigm(g[j]);
    float fg = sigm(g[j + 256]);
    float gg = tanhf(g[j + 512]);
    float og = sigm(g[j + 768]);
    float cn = fg * c[idx] + ig * gg;
    float hn = og * tanhf(cn);
    c[idx] = cn;
    __half h, l; fsplit(hn, h, l);
    long o2 = (long)(d * NB + b) * KX2 + 544 + j;
    X2hi[o2] = h; X2lo[o2] = l;
    int oh = b * NE + d * NH + j;
    hhhi[oh] = h; hhlo[oh] = l;
    int o1 = b * KX1 + d * NH + j;
    X1hi[o1] = h; X1lo[o1] = l;
    if (ffn != nullptr && j < NM) {
        float v = ffn[b * NFT * NM + j];
        __half fh, fl; fsplit(v, fh, fl);
        long of = (long)(d * NB + b) * KX2 + 512 + j;
        X2hi[of] = fh; X2lo[of] = fl;
        if (d == 0) { X1hi[b * KX1 + 512 + j] = fh; X1lo[b * KX1 + 512 + j] = fl; }
    }
}

// ---------------- launch ----------------
extern "C" void kernel_launch(void* const* d_in, const int* in_sizes, int n_in,
                              void* d_out, int out_size)
{
    const float* enc    = (const float*)d_in[0];
    const float* fhist  = (const float*)d_in[1];
    const float* ffut   = (const float*)d_in[3];
    const float* hidden = (const float*)d_in[4];
    const float* cell   = (const float*)d_in[5];
    const float* aW1    = (const float*)d_in[6];
    const float* ab1    = (const float*)d_in[7];
    const float* aW2    = (const float*)d_in[8];
    const float* ab2    = (const float*)d_in[9];
    const float* Wih    = (const float*)d_in[10];
    const float* Whh    = (const float*)d_in[11];
    const float* bih    = (const float*)d_in[12];
    const float* bhh    = (const float*)d_in[13];
    const float* fW1    = (const float*)d_in[14];
    const float* fb1    = (const float*)d_in[15];
    const float* fW2    = (const float*)d_in[16];
    const float* fb2    = (const float*)d_in[17];
    float* out = (float*)d_out;

    __half *pX1, *pTmp, *pX2, *pHH, *pAW1, *pAW2, *pWcat, *pFW1, *pEnc;
    float *pLog, *pAlpha, *pGates, *pC, *pBias2;
    cudaGetSymbolAddress((void**)&pX1, g_X1h);
    cudaGetSymbolAddress((void**)&pTmp, g_tmph);
    cudaGetSymbolAddress((void**)&pX2, g_X2h);
    cudaGetSymbolAddress((void**)&pHH, g_hhh);
    cudaGetSymbolAddress((void**)&pAW1, g_aW1h);
    cudaGetSymbolAddress((void**)&pAW2, g_aW2h);
    cudaGetSymbolAddress((void**)&pWcat, g_Wcath);
    cudaGetSymbolAddress((void**)&pFW1, g_fW1h);
    cudaGetSymbolAddress((void**)&pEnc, g_ench);
    cudaGetSymbolAddress((void**)&pLog, g_logits);
    cudaGetSymbolAddress((void**)&pAlpha, g_alpha);
    cudaGetSymbolAddress((void**)&pGates, g_gates);
    cudaGetSymbolAddress((void**)&pC, g_c);
    cudaGetSymbolAddress((void**)&pBias2, g_bias2);

    const int oX1 = NB * KX1, oTmp = NB * NT, oX2 = 2 * NB * KX2, oHH = NB * NE;
    const int oAW1 = NT * KX1, oAW2 = NT * NT, oWcat = 2 * G4 * KX2, oFW1 = NH * NE;

    setup_kernel<<<512, 256>>>(hidden, cell, ffut, fb2, out, pC, pX1, pX2);
    alpha_kernel<<<NB, 576>>>(ffut, fhist, pAlpha);
    wcat_kernel<<<4096, 256>>>(Wih, Whh, bih, bhh, pWcat, pBias2);
    conv_split<<<1024, 256>>>(aW1, pAW1, NT * KX1);
    conv_split<<<1024, 256>>>(aW2, pAW2, NT * NT);
    conv_split<<<512, 256>>>(fW1, pFW1, NH * NE);
    conv_half4<<<4096, 256>>>((const float4*)enc, (uint2*)pEnc, (int)((long)NB * NT * NE / 4));

    for (int t = 0; t < NFT; t++) {
        // attn1: tmp = tanh(X1 @ aW1^T + ab1), split-half output
        hgemm<1, 1><<<dim3(NB / BM, NT / BN, 1), 128>>>(
            pX1, pX1 + oX1, pAW1, pAW1 + oAW1, ab1,
            nullptr, pTmp, pTmp + oTmp, KX1, NT, 0, 0, 0, 0);
        // attn2: logits = tmp @ aW2^T + ab2 (fp32 out)
        hgemm<0, 0><<<dim3(NB / BM, NT / BN, 1), 128>>>(
            pTmp, pTmp + oTmp, pAW2, pAW2 + oAW2, ab2,
            pLog, nullptr, nullptr, NT, NT, 0, 0, 0, 0);
        // ctx -> X2[:, 0:512] both dirs
        ctx_kernel<<<dim3(NE / 256, NB, 1), 128>>>(pLog, pAlpha, pEnc, pX2, pX2 + oX2);
        // gates = X2 @ Wcat^T + bias2, both dirs via z
        hgemm<0, 0><<<dim3(NB / BM, G4 / BN, 2), 128>>>(
            pX2, pX2 + oX2, pWcat, pWcat + oWcat, pBias2,
            pGates, nullptr, nullptr, KX2, G4,
            (long)NB * KX2, (long)G4 * KX2, (long)G4, (long)NB * G4);
        // LSTM update + forward h / ff[t+1]
        const float* ffn = (t + 1 < NFT) ? (ffut + (t + 1) * NM) : nullptr;
        lstm_kernel<<<2 * NB * NH / 256, 256>>>(pGates, pC, pX1, pX1 + oX1,
                                                pX2, pX2 + oX2, pHH, pHH + oHH, ffn);
        // y[:, t] += relu(hh @ fW1^T + fb1) . fW2
        hgemm_fc<<<dim3(NB / BM, NH / BN, 1), 128>>>(
            pHH, pHH + oHH, pFW1, pFW1 + oFW1, fb1, fW2, out, NE, t);
    }
    (void)in_sizes; (void)n_in; (void)out_size;
}

// round 6
// speedup vs baseline: 2.2598x; 1.7001x over previous
#include <cuda_runtime.h>
#include <cuda_fp16.h>
#include <mma.h>
using namespace nvcuda;

// ---------------- problem constants ----------------
constexpr int NB   = 256;
constexpr int NT   = 576;
constexpr int NFT  = 24;
constexpr int NM   = 32;
constexpr int NH   = 256;
constexpr int NE   = 512;
constexpr int KX1  = 544;
constexpr int KX2  = 800;
constexpr int G4   = 1024;
constexpr float EPSC = 1e-6f;

constexpr int BM = 32;
constexpr int KT = 32;
constexpr int SK = KT + 8;   // smem row stride (halves)

// lo-half offsets
constexpr int oX1  = NB * KX1;
constexpr int oTmp = NB * NT;
constexpr int oX2  = 2 * NB * KX2;       // lo offset within one X2 buffer
constexpr int sX2B = 2 * 2 * NB * KX2;   // stride between X2 ping-pong buffers
constexpr int oHH  = NB * NE;
constexpr int oAW1 = NT * KX1;
constexpr int oAW2 = NT * NT;
constexpr int oWcat = 2 * G4 * KX2;
constexpr int oFW1 = NH * NE;

// ---------------- scratch (device globals) ----------------
__device__ __align__(16) __half g_X1h[2 * NB * KX1];
__device__ __align__(16) __half g_tmph[2 * NB * NT];
__device__ __align__(16) __half g_X2h[2 * sX2B];          // ping-pong buffers
__device__ __align__(16) __half g_hhh[2 * NB * NE];
__device__ __align__(16) __half g_aW1h[2 * NT * KX1];
__device__ __align__(16) __half g_aW2h[2 * NT * NT];
__device__ __align__(16) __half g_Wcath[2 * 2 * G4 * KX2];
__device__ __align__(16) __half g_fW1h[2 * NH * NE];
__device__ __align__(16) __half g_ench[(long)NB * NT * NE];
__device__ __align__(16) float g_logits[NB * NT];
__device__ __align__(16) float g_alpha[NB * NFT];
__device__ __align__(16) float g_c[2 * NB * NH];
__device__ __align__(16) float g_bias2[2 * G4];

__device__ __forceinline__ float sigm(float x) { return 1.0f / (1.0f + expf(-x)); }
__device__ __forceinline__ void fsplit(float v, __half& hi, __half& lo) {
    hi = __float2half(v);
    lo = __float2half(v - __half2float(hi));
}
__device__ __forceinline__ void cpa16(void* d, const void* s) {
    unsigned sd = (unsigned)__cvta_generic_to_shared(d);
    asm volatile("cp.async.cg.shared.global [%0], [%1], 16;" :: "r"(sd), "l"(s));
}
__device__ __forceinline__ void cp_commit() { asm volatile("cp.async.commit_group;"); }
template<int N_> __device__ __forceinline__ void cp_wait() {
    asm volatile("cp.async.wait_group %0;" :: "n"(N_));
}

// ---------------- one-time setup (initial state -> X1 and X2 buffer 0) ----------------
__global__ void setup_kernel(const float* __restrict__ hidden, const float* __restrict__ cell,
                             const float* __restrict__ ff, const float* __restrict__ fb2,
                             float* __restrict__ out, float* __restrict__ c,
                             __half* __restrict__ X1, __half* __restrict__ X2)
{
    const int N0 = NB * NFT;
    const int N1 = 2 * NB * NH;
    const int N2 = NB * KX1;
    const int N3 = 2 * NB * 288;
    const int total = N0 + N1 + N2 + N3;
    for (int i = blockIdx.x * blockDim.x + threadIdx.x; i < total; i += gridDim.x * blockDim.x) {
        int r = i;
        if (r < N0) { out[r] = fb2[0]; continue; }
        r -= N0;
        if (r < N1) { c[r] = cell[r]; continue; }
        r -= N1;
        if (r < N2) {
            int b = r / KX1, k = r % KX1;
            float v;
            if (k < 512) v = hidden[(k < 256 ? 0 : 1) * NB * NH + b * NH + (k & 255)];
            else         v = ff[b * NFT * NM + (k - 512)];
            __half h, l; fsplit(v, h, l);
            X1[r] = h; X1[oX1 + r] = l; continue;
        }
        r -= N2;
        int d = r / (NB * 288); int r2 = r % (NB * 288);
        int b = r2 / 288, k = r2 % 288;
        float v = (k < NM) ? ff[b * NFT * NM + k]
                           : hidden[d * NB * NH + b * NH + (k - NM)];
        int o = (d * NB + b) * KX2 + 512 + k;
        __half h, l; fsplit(v, h, l);
        X2[o] = h; X2[oX2 + o] = l;
    }
}

// ---------------- alpha (once) ----------------
__global__ void alpha_kernel(const float* __restrict__ ff, const float* __restrict__ fh,
                             float* __restrict__ alpha)
{
    int b = blockIdx.x, tid = threadIdx.x;
    int f = tid / 24, p = tid % 24;
    __shared__ float dist[24][24];
    __shared__ float dp[24];
    const float* x = ff + (b * NFT + f) * NM;
    const float* y = fh + ((long)b * NT + p * 24 + f) * NM;
    float s = 0.0f;
#pragma unroll
    for (int m = 0; m < NM; m++) { float d = x[m] - y[m] + EPSC; s += d * d; }
    dist[f][p] = sqrtf(s);
    __syncthreads();
    if (p == 0) { float t = 0.0f; for (int q = 0; q < 24; q++) t += dist[f][q]; dp[f] = 1.0f / t; }
    __syncthreads();
    if (tid == 0) {
        float mx = -1e30f;
        for (int q = 0; q < 24; q++) mx = fmaxf(mx, dp[q]);
        float e[24]; float ss = 0.0f;
        for (int q = 0; q < 24; q++) { e[q] = expf(dp[q] - mx); ss += e[q]; }
        float inv = 1.0f / ss;
        for (int q = 0; q < 24; q++) alpha[b * 24 + q] = e[q] * inv;
    }
}

// ---------------- pack gate-interleaved [W_ih | W_hh] split + combined bias (once) ----
// new column n' = j*4 + g  for original row n = g*256 + j  (g = gate i/f/g/o)
__global__ void wcat_kernel(const float* __restrict__ Wih, const float* __restrict__ Whh,
                            const float* __restrict__ bih, const float* __restrict__ bhh,
                            __half* __restrict__ Wcat, float* __restrict__ bias2)
{
    const int total = 2 * G4 * KX2;
    for (int i = blockIdx.x * blockDim.x + threadIdx.x; i < total; i += gridDim.x * blockDim.x) {
        int d = i / (G4 * KX2); int r = i % (G4 * KX2);
        int np = r / KX2, k = r % KX2;
        int n = (np & 3) * 256 + (np >> 2);
        float v = (k < KX1) ? Wih[(long)(d * G4 + n) * KX1 + k]
                            : Whh[(long)(d * G4 + n) * NH + (k - KX1)];
        __half h, l; fsplit(v, h, l);
        Wcat[i] = h; Wcat[total + i] = l;
    }
    int tid = blockIdx.x * blockDim.x + threadIdx.x;
    if (tid < 2 * G4) {
        int d = tid / G4, np = tid % G4;
        int n = (np & 3) * 256 + (np >> 2);
        bias2[tid] = bih[d * G4 + n] + bhh[d * G4 + n];
    }
}

// ---------------- converters ----------------
__global__ void conv_split(const float* __restrict__ src, __half* __restrict__ dst, int n)
{
    for (int i = blockIdx.x * blockDim.x + threadIdx.x; i < n; i += gridDim.x * blockDim.x) {
        __half h, l; fsplit(src[i], h, l);
        dst[i] = h; dst[n + i] = l;
    }
}

__global__ void conv_half4(const float4* __restrict__ src, uint2* __restrict__ dst, int n4)
{
    for (int i = blockIdx.x * blockDim.x + threadIdx.x; i < n4; i += gridDim.x * blockDim.x) {
        float4 v = src[i];
        __half2 a = __floats2half2_rn(v.x, v.y);
        __half2 b = __floats2half2_rn(v.z, v.w);
        uint2 u;
        u.x = *reinterpret_cast<unsigned*>(&a);
        u.y = *reinterpret_cast<unsigned*>(&b);
        dst[i] = u;
    }
}

// ---------------- double-buffered split-fp16 tensor-core GEMM ----------------
// EPI: 0 = fp32 out, 1 = tanh + split-half out, 2 = LSTM cell (BN=64, interleaved gates;
//      X2out is the NEXT ping-pong buffer — never the A operand), 3 = fc relu-dot (BN=32)
template<int BN, int EPI>
__global__ __launch_bounds__(128) void hgemm2(
    const __half* __restrict__ Ahi, const __half* __restrict__ Alo,
    const __half* __restrict__ Whi, const __half* __restrict__ Wlo,
    const float* __restrict__ bias, int K, int N,
    long sA, long sW, long sB,
    float* __restrict__ Cf, long sC,
    __half* __restrict__ Chi, __half* __restrict__ Clo,
    float* __restrict__ cst, __half* __restrict__ X1, __half* __restrict__ X2out,
    __half* __restrict__ hh,
    const float* __restrict__ w2, float* __restrict__ out, int tstep)
{
    const long z = blockIdx.z;
    Ahi += z * sA; Alo += z * sA; Whi += z * sW; Wlo += z * sW; bias += z * sB;
    __shared__ __align__(16) __half As[2][2][BM][SK];
    __shared__ __align__(16) __half Ws[2][2][BN][SK];
    __shared__ float Cs[BM][BN + 4];
    __shared__ float red[128];
    const int tid = threadIdx.x;
    const int m0 = blockIdx.x * BM, n0 = blockIdx.y * BN;
    const int warp = tid >> 5, wm = warp >> 1, wn = warp & 1;
    const int ar = tid >> 2, ac = (tid & 3) * 8;
    const int nk = K / KT;

    wmma::fragment<wmma::accumulator, 16, 16, 16, float> c0, c1;
    wmma::fill_fragment(c0, 0.0f);
    if (BN == 64) wmma::fill_fragment(c1, 0.0f);

    // prologue: stage 0
    {
        cpa16(&As[0][0][ar][ac], Ahi + (long)(m0 + ar) * K + ac);
        cpa16(&As[0][1][ar][ac], Alo + (long)(m0 + ar) * K + ac);
        cpa16(&Ws[0][0][ar][ac], Whi + (long)(n0 + ar) * K + ac);
        cpa16(&Ws[0][1][ar][ac], Wlo + (long)(n0 + ar) * K + ac);
        if (BN == 64) {
            cpa16(&Ws[0][0][ar + 32][ac], Whi + (long)(n0 + ar + 32) * K + ac);
            cpa16(&Ws[0][1][ar + 32][ac], Wlo + (long)(n0 + ar + 32) * K + ac);
        }
        cp_commit();
    }

    for (int kt = 0; kt < nk; kt++) {
        const int cur = kt & 1;
        if (kt + 1 < nk) {
            const int st = cur ^ 1;
            const int k0 = (kt + 1) * KT;
            cpa16(&As[st][0][ar][ac], Ahi + (long)(m0 + ar) * K + k0 + ac);
            cpa16(&As[st][1][ar][ac], Alo + (long)(m0 + ar) * K + k0 + ac);
            cpa16(&Ws[st][0][ar][ac], Whi + (long)(n0 + ar) * K + k0 + ac);
            cpa16(&Ws[st][1][ar][ac], Wlo + (long)(n0 + ar) * K + k0 + ac);
            if (BN == 64) {
                cpa16(&Ws[st][0][ar + 32][ac], Whi + (long)(n0 + ar + 32) * K + k0 + ac);
                cpa16(&Ws[st][1][ar + 32][ac], Wlo + (long)(n0 + ar + 32) * K + k0 + ac);
            }
            cp_commit();
            cp_wait<1>();
        } else {
            cp_wait<0>();
        }
        __syncthreads();
#pragma unroll
        for (int sub = 0; sub < KT; sub += 16) {
            wmma::fragment<wmma::matrix_a, 16, 16, 16, __half, wmma::row_major> ah, al;
            wmma::load_matrix_sync(ah, &As[cur][0][wm * 16][sub], SK);
            wmma::load_matrix_sync(al, &As[cur][1][wm * 16][sub], SK);
            wmma::fragment<wmma::matrix_b, 16, 16, 16, __half, wmma::col_major> bh, bl;
            if (BN == 64) {
                wmma::load_matrix_sync(bh, &Ws[cur][0][wn * 32][sub], SK);
                wmma::load_matrix_sync(bl, &Ws[cur][1][wn * 32][sub], SK);
                wmma::mma_sync(c0, ah, bh, c0);
                wmma::mma_sync(c0, ah, bl, c0);
                wmma::mma_sync(c0, al, bh, c0);
                wmma::load_matrix_sync(bh, &Ws[cur][0][wn * 32 + 16][sub], SK);
                wmma::load_matrix_sync(bl, &Ws[cur][1][wn * 32 + 16][sub], SK);
                wmma::mma_sync(c1, ah, bh, c1);
                wmma::mma_sync(c1, ah, bl, c1);
                wmma::mma_sync(c1, al, bh, c1);
            } else {
                wmma::load_matrix_sync(bh, &Ws[cur][0][wn * 16][sub], SK);
                wmma::load_matrix_sync(bl, &Ws[cur][1][wn * 16][sub], SK);
                wmma::mma_sync(c0, ah, bh, c0);
                wmma::mma_sync(c0, ah, bl, c0);
                wmma::mma_sync(c0, al, bh, c0);
            }
        }
        __syncthreads();
    }

    if (BN == 64) {
        wmma::store_matrix_sync(&Cs[wm * 16][wn * 32], c0, BN + 4, wmma::mem_row_major);
        wmma::store_matrix_sync(&Cs[wm * 16][wn * 32 + 16], c1, BN + 4, wmma::mem_row_major);
    } else {
        wmma::store_matrix_sync(&Cs[wm * 16][wn * 16], c0, BN + 4, wmma::mem_row_major);
    }
    __syncthreads();

    if (EPI == 0) {
        for (int idx = tid; idx < BM * BN; idx += 128) {
            int m = idx / BN, n = idx % BN;
            Cf[(long)(m0 + m) * N + n0 + n + z * sC] = Cs[m][n] + bias[n0 + n];
        }
    } else if (EPI == 1) {
        for (int idx = tid; idx < BM * BN; idx += 128) {
            int m = idx / BN, n = idx % BN;
            float v = tanhf(Cs[m][n] + bias[n0 + n]);
            long o = (long)(m0 + m) * N + n0 + n;
            __half h = __float2half(v);
            Chi[o] = h;
            Clo[o] = __float2half(v - __half2float(h));
        }
    } else if (EPI == 2) {
        const int d = (int)z;
        for (int idx = tid; idx < BM * 16; idx += 128) {
            int m = idx >> 4, jj = idx & 15;
            int b = m0 + m, j = (n0 >> 2) + jj;
            float ig = sigm(Cs[m][jj * 4 + 0] + bias[n0 + jj * 4 + 0]);
            float fg = sigm(Cs[m][jj * 4 + 1] + bias[n0 + jj * 4 + 1]);
            float gg = tanhf(Cs[m][jj * 4 + 2] + bias[n0 + jj * 4 + 2]);
            float og = sigm(Cs[m][jj * 4 + 3] + bias[n0 + jj * 4 + 3]);
            int ci = (d * NB + b) * NH + j;
            float cn = fg * cst[ci] + ig * gg;
            float hn = og * tanhf(cn);
            cst[ci] = cn;
            __half h, l; fsplit(hn, h, l);
            long o2 = (long)(d * NB + b) * KX2 + 544 + j;   // into NEXT X2 buffer
            X2out[o2] = h; X2out[o2 + oX2] = l;
            int oh = b * NE + d * NH + j;
            hh[oh] = h; hh[oh + oHH] = l;
            int o1 = b * KX1 + d * NH + j;
            X1[o1] = h; X1[o1 + oX1] = l;
        }
    } else {  // EPI 3, BN == 32
        int r = tid >> 2, g = tid & 3;
        float s = 0.0f;
#pragma unroll
        for (int jj = 0; jj < 8; jj++) {
            int n = g * 8 + jj;
            float v = fmaxf(Cs[r][n] + bias[n0 + n], 0.0f);
            s += v * w2[n0 + n];
        }
        red[tid] = s;
        __syncthreads();
        if (tid < 32) {
            float tsum = red[tid * 4] + red[tid * 4 + 1] + red[tid * 4 + 2] + red[tid * 4 + 3];
            atomicAdd(&out[(m0 + tid) * NFT + tstep], tsum);
        }
    }
}

// ---------------- ctx: softmax(*alpha) + high-MLP enc stream; also scatters ff ----------------
__global__ __launch_bounds__(128) void ctx_kernel(
    const float* __restrict__ logits, const float* __restrict__ alpha,
    const __half* __restrict__ ench, __half* __restrict__ X2h, __half* __restrict__ X1h,
    const float* __restrict__ ffC, const float* __restrict__ ffN)
{
    const int b = blockIdx.y;
    const int e0 = blockIdx.x * 256;
    const int tid = threadIdx.x;
    __shared__ float wt[NT];
    __shared__ float sred[4];
    const float* lrow = logits + b * NT;

    float mx = -1e30f;
    for (int t = tid; t < NT; t += 128) mx = fmaxf(mx, lrow[t]);
#pragma unroll
    for (int o = 16; o > 0; o >>= 1) mx = fmaxf(mx, __shfl_xor_sync(0xffffffffu, mx, o));
    if ((tid & 31) == 0) sred[tid >> 5] = mx;
    __syncthreads();
    mx = fmaxf(fmaxf(sred[0], sred[1]), fmaxf(sred[2], sred[3]));
    __syncthreads();

    float s = 0.0f;
    for (int t = tid; t < NT; t += 128) { float e = expf(lrow[t] - mx); wt[t] = e; s += e; }
#pragma unroll
    for (int o = 16; o > 0; o >>= 1) s += __shfl_xor_sync(0xffffffffu, s, o);
    if ((tid & 31) == 0) sred[tid >> 5] = s;
    __syncthreads();
    s = sred[0] + sred[1] + sred[2] + sred[3];
    float inv = 1.0f / s;
    for (int t = tid; t < NT; t += 128) wt[t] *= inv * alpha[b * 24 + t / 24];
    __syncthreads();

    const __half2* eb = (const __half2*)(ench + ((long)b * NT) * NE + e0) + tid;
    float ax = 0, ay = 0, bx = 0, by = 0, cx = 0, cy = 0, dx = 0, dy = 0;
#pragma unroll 1
    for (int t = 0; t < NT; t += 8) {
        float2 v0 = __half22float2(eb[(t + 0) * 256]);
        float2 v1 = __half22float2(eb[(t + 1) * 256]);
        float2 v2 = __half22float2(eb[(t + 2) * 256]);
        float2 v3 = __half22float2(eb[(t + 3) * 256]);
        float2 v4 = __half22float2(eb[(t + 4) * 256]);
        float2 v5 = __half22float2(eb[(t + 5) * 256]);
        float2 v6 = __half22float2(eb[(t + 6) * 256]);
        float2 v7 = __half22float2(eb[(t + 7) * 256]);
        ax += wt[t + 0] * v0.x; ay += wt[t + 0] * v0.y;
        bx += wt[t + 1] * v1.x; by += wt[t + 1] * v1.y;
        cx += wt[t + 2] * v2.x; cy += wt[t + 2] * v2.y;
        dx += wt[t + 3] * v3.x; dy += wt[t + 3] * v3.y;
        ax += wt[t + 4] * v4.x; ay += wt[t + 4] * v4.y;
        bx += wt[t + 5] * v5.x; by += wt[t + 5] * v5.y;
        cx += wt[t + 6] * v6.x; cy += wt[t + 6] * v6.y;
        dx += wt[t + 7] * v7.x; dy += wt[t + 7] * v7.y;
    }
    float vx = (ax + bx) + (cx + dx), vy = (ay + by) + (cy + dy);
    __half hx, lx, hy, ly;
    fsplit(vx, hx, lx); fsplit(vy, hy, ly);
    long o0 = (long)b * KX2 + e0 + 2 * tid;
    long o1 = (long)(NB + b) * KX2 + e0 + 2 * tid;
    X2h[o0] = hx; X2h[o0 + 1] = hy; X2h[oX2 + o0] = lx; X2h[oX2 + o0 + 1] = ly;
    X2h[o1] = hx; X2h[o1 + 1] = hy; X2h[oX2 + o1] = lx; X2h[oX2 + o1 + 1] = ly;

    // ff scatter: X2(cur) <- ff[t] (both dirs), X1 <- ff[t+1]
    if (blockIdx.x == 0 && tid < NM) {
        float v = ffC[b * NFT * NM + tid];
        __half h, l; fsplit(v, h, l);
        long oa = (long)b * KX2 + 512 + tid;
        long ob = (long)(NB + b) * KX2 + 512 + tid;
        X2h[oa] = h; X2h[oX2 + oa] = l;
        X2h[ob] = h; X2h[oX2 + ob] = l;
        if (ffN != nullptr) {
            float v2 = ffN[b * NFT * NM + tid];
            __half h2, l2; fsplit(v2, h2, l2);
            int oc = b * KX1 + 512 + tid;
            X1h[oc] = h2; X1h[oX1 + oc] = l2;
        }
    }
}

// ---------------- launch ----------------
extern "C" void kernel_launch(void* const* d_in, const int* in_sizes, int n_in,
                              void* d_out, int out_size)
{
    const float* enc    = (const float*)d_in[0];
    const float* fhist  = (const float*)d_in[1];
    const float* ffut   = (const float*)d_in[3];
    const float* hidden = (const float*)d_in[4];
    const float* cell   = (const float*)d_in[5];
    const float* aW1    = (const float*)d_in[6];
    const float* ab1    = (const float*)d_in[7];
    const float* aW2    = (const float*)d_in[8];
    const float* ab2    = (const float*)d_in[9];
    const float* Wih    = (const float*)d_in[10];
    const float* Whh    = (const float*)d_in[11];
    const float* bih    = (const float*)d_in[12];
    const float* bhh    = (const float*)d_in[13];
    const float* fW1    = (const float*)d_in[14];
    const float* fb1    = (const float*)d_in[15];
    const float* fW2    = (const float*)d_in[16];
    const float* fb2    = (const float*)d_in[17];
    float* out = (float*)d_out;

    __half *pX1, *pTmp, *pX2, *pHH, *pAW1, *pAW2, *pWcat, *pFW1, *pEnc;
    float *pLog, *pAlpha, *pC, *pBias2;
    cudaGetSymbolAddress((void**)&pX1, g_X1h);
    cudaGetSymbolAddress((void**)&pTmp, g_tmph);
    cudaGetSymbolAddress((void**)&pX2, g_X2h);
    cudaGetSymbolAddress((void**)&pHH, g_hhh);
    cudaGetSymbolAddress((void**)&pAW1, g_aW1h);
    cudaGetSymbolAddress((void**)&pAW2, g_aW2h);
    cudaGetSymbolAddress((void**)&pWcat, g_Wcath);
    cudaGetSymbolAddress((void**)&pFW1, g_fW1h);
    cudaGetSymbolAddress((void**)&pEnc, g_ench);
    cudaGetSymbolAddress((void**)&pLog, g_logits);
    cudaGetSymbolAddress((void**)&pAlpha, g_alpha);
    cudaGetSymbolAddress((void**)&pC, g_c);
    cudaGetSymbolAddress((void**)&pBias2, g_bias2);

    setup_kernel<<<512, 256>>>(hidden, cell, ffut, fb2, out, pC, pX1, pX2 /* buffer 0 */);
    alpha_kernel<<<NB, 576>>>(ffut, fhist, pAlpha);
    wcat_kernel<<<4096, 256>>>(Wih, Whh, bih, bhh, pWcat, pBias2);
    conv_split<<<1024, 256>>>(aW1, pAW1, NT * KX1);
    conv_split<<<1024, 256>>>(aW2, pAW2, NT * NT);
    conv_split<<<512, 256>>>(fW1, pFW1, NH * NE);
    conv_half4<<<4096, 256>>>((const float4*)enc, (uint2*)pEnc, (int)((long)NB * NT * NE / 4));

    for (int t = 0; t < NFT; t++) {
        __half* X2cur = pX2 + (t & 1) * sX2B;         // gates input this step
        __half* X2nxt = pX2 + ((t + 1) & 1) * sX2B;   // h written for next step

        // attn1: tmp = tanh(X1 @ aW1^T + ab1) -> split halves
        hgemm2<32, 1><<<dim3(NB / BM, NT / 32, 1), 128>>>(
            pX1, pX1 + oX1, pAW1, pAW1 + oAW1, ab1, KX1, NT, 0, 0, 0,
            nullptr, 0, pTmp, pTmp + oTmp,
            nullptr, nullptr, nullptr, nullptr, nullptr, nullptr, 0);
        // attn2: logits = tmp @ aW2^T + ab2 (fp32)
        hgemm2<32, 0><<<dim3(NB / BM, NT / 32, 1), 128>>>(
            pTmp, pTmp + oTmp, pAW2, pAW2 + oAW2, ab2, NT, NT, 0, 0, 0,
            pLog, 0, nullptr, nullptr,
            nullptr, nullptr, nullptr, nullptr, nullptr, nullptr, 0);
        // ctx -> X2cur ctx slice (both dirs); scatters ff[t] into X2cur, ff[t+1] into X1
        const float* ffN = (t + 1 < NFT) ? (ffut + (t + 1) * NM) : nullptr;
        ctx_kernel<<<dim3(NE / 256, NB, 1), 128>>>(pLog, pAlpha, pEnc, X2cur, pX1,
                                                   ffut + t * NM, ffN);
        // gates GEMM (interleaved) + fused LSTM cell; h -> X1 / X2nxt / hh, c updated
        hgemm2<64, 2><<<dim3(NB / BM, G4 / 64, 2), 128>>>(
            X2cur, X2cur + oX2, pWcat, pWcat + oWcat, pBias2, KX2, G4,
            (long)NB * KX2, (long)G4 * KX2, (long)G4,
            nullptr, 0, nullptr, nullptr,
            pC, pX1, X2nxt, pHH, nullptr, nullptr, 0);
        // fc_final: out[:, t] += relu(hh @ fW1^T + fb1) . fW2
        hgemm2<32, 3><<<dim3(NB / BM, NH / 32, 1), 128>>>(
            pHH, pHH + oHH, pFW1, pFW1 + oFW1, fb1, NE, NH, 0, 0, 0,
            nullptr, 0, nullptr, nullptr,
            nullptr, nullptr, nullptr, nullptr, fW2, out, t);
    }
    (void)in_sizes; (void)n_in; (void)out_size;
}